// round 3
// baseline (speedup 1.0000x reference)
#include <cuda_runtime.h>
#include <cuda_bf16.h>

#define NODES_MAX 50000
#define D 128

// Scratch: aggregation buffer. 16B-aligned: accessed via float4 and
// red.global.add.v4.f32 (vector ops trap on misaligned addresses).
__device__ __align__(16) float g_agg[(size_t)NODES_MAX * D];

// 1 if src/dst are int64, 0 if int32. Written by detect kernel each launch.
__device__ int g_idx_is_i64;

// ---------------------------------------------------------------------------
// Kernel 0: detect index dtype. For true int64 indices in [0, 50000) every
// high 32-bit word is zero. For int32 data, the "high word" is the next
// index (nonzero w.p. ~1 over 128 samples). Deterministic.
// ---------------------------------------------------------------------------
__global__ void detect_idx_dtype_kernel(const void* __restrict__ src,
                                        int n_edges) {
    __shared__ int any_hi;
    if (threadIdx.x == 0) any_hi = 0;
    __syncthreads();
    int nsample = n_edges < 128 ? n_edges : 128;
    if (threadIdx.x < nsample) {
        // int64 view: element i occupies words (2i, 2i+1)
        int hi = ((const int*)src)[2 * threadIdx.x + 1];
        if (hi != 0) atomicOr(&any_hi, 1);
    }
    __syncthreads();
    if (threadIdx.x == 0) g_idx_is_i64 = any_hi ? 0 : 1;
}

// ---------------------------------------------------------------------------
// Kernel 1: agg[i] = (1 + eps) * feature[i]
// ---------------------------------------------------------------------------
__global__ void init_agg_kernel(const float* __restrict__ feat,
                                const float* __restrict__ eps, int n4) {
    int i = blockIdx.x * blockDim.x + threadIdx.x;
    if (i >= n4) return;
    float s = 1.0f + eps[0];
    float4 v = ((const float4*)feat)[i];
    v.x *= s; v.y *= s; v.z *= s; v.w *= s;
    ((float4*)g_agg)[i] = v;
}

// ---------------------------------------------------------------------------
// Kernel 2: edge scatter. One warp per edge: 32 lanes x float4 = 128 floats.
// feature (25.6MB) is L2-resident; red.v4.f32 quarters L2 atomic-op count.
// ---------------------------------------------------------------------------
__global__ void scatter_edges_kernel(const float* __restrict__ feat,
                                     const void* __restrict__ src,
                                     const void* __restrict__ dst,
                                     int n_edges) {
    int e = blockIdx.x * 8 + (threadIdx.x >> 5);
    if (e >= n_edges) return;
    int lane = threadIdx.x & 31;

    long long s, d;
    if (g_idx_is_i64) {
        s = ((const long long*)src)[e];
        d = ((const long long*)dst)[e];
    } else {
        s = ((const int*)src)[e];
        d = ((const int*)dst)[e];
    }

    float4 v = ((const float4*)(feat + (size_t)s * D))[lane];
    float* ap = g_agg + (size_t)d * D + (size_t)lane * 4;
#if __CUDA_ARCH__ >= 900
    asm volatile("red.global.add.v4.f32 [%0], {%1,%2,%3,%4};"
                 :: "l"(ap), "f"(v.x), "f"(v.y), "f"(v.z), "f"(v.w)
                 : "memory");
#else
    atomicAdd(ap + 0, v.x);
    atomicAdd(ap + 1, v.y);
    atomicAdd(ap + 2, v.z);
    atomicAdd(ap + 3, v.w);
#endif
}

// ---------------------------------------------------------------------------
// Kernel 3: out = relu(agg @ W^T + b)
// TILE_M = 32 rows/block, 256 threads, 4x4 register tile per thread.
// ---------------------------------------------------------------------------
#define TILE_M 32
#define WPAD 132

__global__ __launch_bounds__(256) void gin_gemm_kernel(
    const float* __restrict__ W, const float* __restrict__ bias,
    float* __restrict__ out, int n_nodes) {
    extern __shared__ float sm[];
    float* Wt = sm;               // [128][WPAD]  Wt[k][c] = W[c][k]
    float* hs = sm + D * WPAD;    // [TILE_M][128]

    int tid = threadIdx.x;
    int tx = tid & 31;            // output cols 4*tx .. 4*tx+3
    int ty = tid >> 5;            // rows 4*ty .. 4*ty+3

    for (int idx = tid; idx < D * D; idx += 256) {
        int c = idx >> 7;
        int k = idx & 127;
        Wt[k * WPAD + c] = W[idx];
    }

    int m0 = blockIdx.x * TILE_M;
    for (int idx = tid; idx < TILE_M * (D / 4); idx += 256) {
        int m  = idx >> 5;
        int k4 = idx & 31;
        float4 v = make_float4(0.f, 0.f, 0.f, 0.f);
        if (m0 + m < n_nodes)
            v = ((const float4*)(g_agg + (size_t)(m0 + m) * D))[k4];
        ((float4*)(hs + m * D))[k4] = v;
    }
    __syncthreads();

    float acc[4][4];
#pragma unroll
    for (int i = 0; i < 4; i++)
#pragma unroll
        for (int j = 0; j < 4; j++) acc[i][j] = 0.f;

#pragma unroll 4
    for (int k = 0; k < D; k += 4) {
        float4 w0 = *(const float4*)&Wt[(k + 0) * WPAD + tx * 4];
        float4 w1 = *(const float4*)&Wt[(k + 1) * WPAD + tx * 4];
        float4 w2 = *(const float4*)&Wt[(k + 2) * WPAD + tx * 4];
        float4 w3 = *(const float4*)&Wt[(k + 3) * WPAD + tx * 4];
#pragma unroll
        for (int i = 0; i < 4; i++) {
            float4 hv = *(const float4*)&hs[(ty * 4 + i) * D + k];
            acc[i][0] += hv.x * w0.x + hv.y * w1.x + hv.z * w2.x + hv.w * w3.x;
            acc[i][1] += hv.x * w0.y + hv.y * w1.y + hv.z * w2.y + hv.w * w3.y;
            acc[i][2] += hv.x * w0.z + hv.y * w1.z + hv.z * w2.z + hv.w * w3.z;
            acc[i][3] += hv.x * w0.w + hv.y * w1.w + hv.z * w2.w + hv.w * w3.w;
        }
    }

    float4 bv = *(const float4*)&bias[tx * 4];
#pragma unroll
    for (int i = 0; i < 4; i++) {
        int row = m0 + ty * 4 + i;
        if (row < n_nodes) {
            float4 o;
            o.x = fmaxf(acc[i][0] + bv.x, 0.f);
            o.y = fmaxf(acc[i][1] + bv.y, 0.f);
            o.z = fmaxf(acc[i][2] + bv.z, 0.f);
            o.w = fmaxf(acc[i][3] + bv.w, 0.f);
            ((float4*)(out + (size_t)row * D))[tx] = o;
        }
    }
}

// ---------------------------------------------------------------------------
// Launch: detect -> init -> scatter -> gemm. Graph-capturable, alloc-free.
// ---------------------------------------------------------------------------
extern "C" void kernel_launch(void* const* d_in, const int* in_sizes, int n_in,
                              void* d_out, int out_size) {
    const float* feature = (const float*)d_in[0];
    const void*  src     = d_in[1];
    const void*  dst     = d_in[2];
    const float* W       = (const float*)d_in[3];
    const float* bias    = (const float*)d_in[4];
    const float* eps     = (const float*)d_in[5];
    float*       out     = (float*)d_out;

    int n_nodes = in_sizes[0] / D;
    int n_edges = in_sizes[1];

    static bool smem_ok = false;
    size_t smem = (size_t)(D * WPAD + TILE_M * D) * sizeof(float);  // ~84KB
    if (!smem_ok) {
        cudaFuncSetAttribute(gin_gemm_kernel,
                             cudaFuncAttributeMaxDynamicSharedMemorySize,
                             (int)smem);
        smem_ok = true;
    }

    // 0. detect whether src/dst are int32 or int64
    detect_idx_dtype_kernel<<<1, 128>>>(src, n_edges);

    // 1. agg = (1+eps) * feature
    int n4 = n_nodes * D / 4;
    init_agg_kernel<<<(n4 + 255) / 256, 256>>>(feature, eps, n4);

    // 2. scatter-add edges (8 warps/block, warp per edge)
    scatter_edges_kernel<<<(n_edges + 7) / 8, 256>>>(feature, src, dst, n_edges);

    // 3. fused GEMM + bias + relu
    gin_gemm_kernel<<<(n_nodes + TILE_M - 1) / TILE_M, 256, smem>>>(
        W, bias, out, n_nodes);
}

// round 5
// speedup vs baseline: 1.1469x; 1.1469x over previous
#include <cuda_runtime.h>
#include <cuda_bf16.h>

#define NODES_MAX 50000
#define D 128

// Scratch: aggregation buffer. 16B-aligned (float4 + red.v4.f32 access).
__device__ __align__(16) float g_agg[(size_t)NODES_MAX * D];

// 1 if src/dst are int64, 0 if int32.
__device__ int g_idx_is_i64;

// ---------------------------------------------------------------------------
// Kernel 0: detect index dtype (int32 vs int64) from the bit pattern.
// ---------------------------------------------------------------------------
__global__ void detect_idx_dtype_kernel(const void* __restrict__ src,
                                        int n_edges) {
    __shared__ int any_hi;
    if (threadIdx.x == 0) any_hi = 0;
    __syncthreads();
    int nsample = n_edges < 128 ? n_edges : 128;
    if (threadIdx.x < nsample) {
        int hi = ((const int*)src)[2 * threadIdx.x + 1];
        if (hi != 0) atomicOr(&any_hi, 1);
    }
    __syncthreads();
    if (threadIdx.x == 0) g_idx_is_i64 = any_hi ? 0 : 1;
}

// ---------------------------------------------------------------------------
// Kernel 1: agg = 0 (eps-residual folded into the GEMM tile load).
// ---------------------------------------------------------------------------
__global__ void zero_agg_kernel(int n4) {
    int i = blockIdx.x * blockDim.x + threadIdx.x;
    if (i < n4)
        ((float4*)g_agg)[i] = make_float4(0.f, 0.f, 0.f, 0.f);
}

// ---------------------------------------------------------------------------
// Kernel 2: edge scatter. One warp per edge; red.v4.f32 into g_agg.
// LTS-throughput-bound (~820MB through L2).
// ---------------------------------------------------------------------------
__global__ void scatter_edges_kernel(const float* __restrict__ feat,
                                     const void* __restrict__ src,
                                     const void* __restrict__ dst,
                                     int n_edges) {
    int e = blockIdx.x * 8 + (threadIdx.x >> 5);
    if (e >= n_edges) return;
    int lane = threadIdx.x & 31;

    long long s, d;
    if (g_idx_is_i64) {
        s = ((const long long*)src)[e];
        d = ((const long long*)dst)[e];
    } else {
        s = ((const int*)src)[e];
        d = ((const int*)dst)[e];
    }

    float4 v = ((const float4*)(feat + (size_t)s * D))[lane];
    float* ap = g_agg + (size_t)d * D + (size_t)lane * 4;
#if __CUDA_ARCH__ >= 900
    asm volatile("red.global.add.v4.f32 [%0], {%1,%2,%3,%4};"
                 :: "l"(ap), "f"(v.x), "f"(v.y), "f"(v.z), "f"(v.w)
                 : "memory");
#else
    atomicAdd(ap + 0, v.x);
    atomicAdd(ap + 1, v.y);
    atomicAdd(ap + 2, v.z);
    atomicAdd(ap + 3, v.w);
#endif
}

// ---------------------------------------------------------------------------
// Kernel 3: out = relu(((1+eps)*feat + agg) @ W^T + b)
// Persistent: 296 blocks loop over 64-row tiles; W staged to smem ONCE per
// block. 512 threads, 4x4 register tile each. 2 CTAs/SM -> 32 warps (50% occ).
// ---------------------------------------------------------------------------
#define TILE_M 64
#define WPAD 132
#define GEMM_BLOCKS 296

__global__ __launch_bounds__(512, 2) void gin_gemm_kernel(
    const float* __restrict__ feat, const float* __restrict__ W,
    const float* __restrict__ bias, const float* __restrict__ eps,
    float* __restrict__ out, int n_nodes) {
    extern __shared__ float sm[];
    float* Wt = sm;               // [128][WPAD]  Wt[k][c] = W[c][k]
    float* hs = sm + D * WPAD;    // [TILE_M][128]

    int tid = threadIdx.x;
    int tx = tid & 31;            // output cols 4*tx .. 4*tx+3
    int ty = tid >> 5;            // rows 4*ty .. 4*ty+3 (ty in 0..15)
    float s = 1.0f + eps[0];

    // Stage W transposed once per block.
    for (int idx = tid; idx < D * D; idx += 512) {
        int c = idx >> 7;
        int k = idx & 127;
        Wt[k * WPAD + c] = W[idx];
    }

    float4 bv = *(const float4*)&bias[tx * 4];
    int n_tiles = (n_nodes + TILE_M - 1) / TILE_M;

    for (int t = blockIdx.x; t < n_tiles; t += gridDim.x) {
        int m0 = t * TILE_M;

        __syncthreads();   // protect hs from previous iteration's readers
        // Load h tile: h = s*feat + agg  (float4-coalesced; 4 per thread)
        for (int idx = tid; idx < TILE_M * (D / 4); idx += 512) {
            int m  = idx >> 5;
            int k4 = idx & 31;
            float4 v = make_float4(0.f, 0.f, 0.f, 0.f);
            if (m0 + m < n_nodes) {
                float4 f = ((const float4*)(feat  + (size_t)(m0 + m) * D))[k4];
                float4 a = ((const float4*)(g_agg + (size_t)(m0 + m) * D))[k4];
                v.x = fmaf(s, f.x, a.x);
                v.y = fmaf(s, f.y, a.y);
                v.z = fmaf(s, f.z, a.z);
                v.w = fmaf(s, f.w, a.w);
            }
            ((float4*)(hs + m * D))[k4] = v;
        }
        __syncthreads();

        float acc[4][4];
#pragma unroll
        for (int i = 0; i < 4; i++)
#pragma unroll
            for (int j = 0; j < 4; j++) acc[i][j] = 0.f;

#pragma unroll 4
        for (int k = 0; k < D; k += 4) {
            float4 w0 = *(const float4*)&Wt[(k + 0) * WPAD + tx * 4];
            float4 w1 = *(const float4*)&Wt[(k + 1) * WPAD + tx * 4];
            float4 w2 = *(const float4*)&Wt[(k + 2) * WPAD + tx * 4];
            float4 w3 = *(const float4*)&Wt[(k + 3) * WPAD + tx * 4];
#pragma unroll
            for (int i = 0; i < 4; i++) {
                float4 hv = *(const float4*)&hs[(ty * 4 + i) * D + k];
                acc[i][0] += hv.x * w0.x + hv.y * w1.x + hv.z * w2.x + hv.w * w3.x;
                acc[i][1] += hv.x * w0.y + hv.y * w1.y + hv.z * w2.y + hv.w * w3.y;
                acc[i][2] += hv.x * w0.z + hv.y * w1.z + hv.z * w2.z + hv.w * w3.z;
                acc[i][3] += hv.x * w0.w + hv.y * w1.w + hv.z * w2.w + hv.w * w3.w;
            }
        }

#pragma unroll
        for (int i = 0; i < 4; i++) {
            int row = m0 + ty * 4 + i;
            if (row < n_nodes) {
                float4 o;
                o.x = fmaxf(acc[i][0] + bv.x, 0.f);
                o.y = fmaxf(acc[i][1] + bv.y, 0.f);
                o.z = fmaxf(acc[i][2] + bv.z, 0.f);
                o.w = fmaxf(acc[i][3] + bv.w, 0.f);
                ((float4*)(out + (size_t)row * D))[tx] = o;
            }
        }
    }
}

// ---------------------------------------------------------------------------
// Launch: detect -> zero -> scatter -> gemm. Graph-capturable, alloc-free.
// ---------------------------------------------------------------------------
extern "C" void kernel_launch(void* const* d_in, const int* in_sizes, int n_in,
                              void* d_out, int out_size) {
    const float* feature = (const float*)d_in[0];
    const void*  src     = d_in[1];
    const void*  dst     = d_in[2];
    const float* W       = (const float*)d_in[3];
    const float* bias    = (const float*)d_in[4];
    const float* eps     = (const float*)d_in[5];
    float*       out     = (float*)d_out;

    int n_nodes = in_sizes[0] / D;
    int n_edges = in_sizes[1];

    static bool smem_ok = false;
    size_t smem = (size_t)(D * WPAD + TILE_M * D) * sizeof(float);  // ~100KB
    if (!smem_ok) {
        cudaFuncSetAttribute(gin_gemm_kernel,
                             cudaFuncAttributeMaxDynamicSharedMemorySize,
                             (int)smem);
        smem_ok = true;
    }

    // 0. index dtype detection
    detect_idx_dtype_kernel<<<1, 128>>>(src, n_edges);

    // 1. agg = 0
    int n4 = n_nodes * D / 4;
    zero_agg_kernel<<<(n4 + 255) / 256, 256>>>(n4);

    // 2. scatter-add edges
    scatter_edges_kernel<<<(n_edges + 7) / 8, 256>>>(feature, src, dst, n_edges);

    // 3. persistent fused GEMM + eps-residual + bias + relu
    gin_gemm_kernel<<<GEMM_BLOCKS, 512, smem>>>(
        feature, W, bias, eps, out, n_nodes);
}

// round 6
// speedup vs baseline: 1.4830x; 1.2931x over previous
#include <cuda_runtime.h>
#include <cuda_bf16.h>

#define NODES_MAX 50048
#define EMAX      2000000
#define D 128
#define SCAN_B 1024

// Scratch (alloc-free rule -> __device__ globals)
__device__ __align__(16) float g_agg[(size_t)NODES_MAX * D];  // holds h
__device__ int g_idx_is_i64;
__device__ int g_deg[NODES_MAX];
__device__ int g_scan[NODES_MAX];        // per-block inclusive scans
__device__ int g_blk[64];                // block sums
__device__ int g_blk_exc[64];            // exclusive block offsets
__device__ int g_csr_off[NODES_MAX + 1];
__device__ int g_cursor[NODES_MAX];
__device__ int g_csr_src[EMAX];

// ---------------------------------------------------------------------------
// Kernel 0: detect index dtype (int32 vs int64) from the bit pattern.
// ---------------------------------------------------------------------------
__global__ void detect_idx_dtype_kernel(const void* __restrict__ src,
                                        int n_edges) {
    __shared__ int any_hi;
    if (threadIdx.x == 0) any_hi = 0;
    __syncthreads();
    int nsample = n_edges < 128 ? n_edges : 128;
    if (threadIdx.x < nsample) {
        int hi = ((const int*)src)[2 * threadIdx.x + 1];
        if (hi != 0) atomicOr(&any_hi, 1);
    }
    __syncthreads();
    if (threadIdx.x == 0) g_idx_is_i64 = any_hi ? 0 : 1;
}

__device__ __forceinline__ int load_idx(const void* p, int e) {
    return g_idx_is_i64 ? (int)((const long long*)p)[e] : ((const int*)p)[e];
}

// ---------------------------------------------------------------------------
// CSR construction: zero -> histogram -> scan(x3) -> reorder
// ---------------------------------------------------------------------------
__global__ void zero_deg_kernel(int n) {
    int i = blockIdx.x * blockDim.x + threadIdx.x;
    if (i < n) g_deg[i] = 0;
}

__global__ void hist_kernel(const void* __restrict__ dst, int n_edges) {
    int e = blockIdx.x * blockDim.x + threadIdx.x;
    if (e >= n_edges) return;
    atomicAdd(&g_deg[load_idx(dst, e)], 1);
}

// Per-block inclusive Hillis-Steele scan of g_deg.
__global__ void scan1_kernel(int n) {
    __shared__ int s[SCAN_B];
    int t = threadIdx.x;
    int i = blockIdx.x * SCAN_B + t;
    int v = (i < n) ? g_deg[i] : 0;
    s[t] = v;
    __syncthreads();
    for (int o = 1; o < SCAN_B; o <<= 1) {
        int x = (t >= o) ? s[t - o] : 0;
        __syncthreads();
        s[t] += x;
        __syncthreads();
    }
    if (i < n) g_scan[i] = s[t];
    if (t == SCAN_B - 1) g_blk[blockIdx.x] = s[t];
}

// Single-block scan of block sums -> exclusive block offsets.
__global__ void scan2_kernel(int nblk) {
    __shared__ int s[64];
    int t = threadIdx.x;
    int v = (t < nblk) ? g_blk[t] : 0;
    s[t] = v;
    __syncthreads();
    for (int o = 1; o < 64; o <<= 1) {
        int x = (t >= o) ? s[t - o] : 0;
        __syncthreads();
        s[t] += x;
        __syncthreads();
    }
    if (t < nblk) g_blk_exc[t] = s[t] - v;
}

// Combine: exclusive global offsets; init cursors; write sentinel.
__global__ void scan3_kernel(int n) {
    int i = blockIdx.x * blockDim.x + threadIdx.x;
    if (i >= n) return;
    int off = g_blk_exc[i / SCAN_B] + g_scan[i] - g_deg[i];
    g_csr_off[i] = off;
    g_cursor[i]  = off;
    if (i == n - 1) g_csr_off[n] = off + g_deg[i];
}

__global__ void reorder_kernel(const void* __restrict__ src,
                               const void* __restrict__ dst, int n_edges) {
    int e = blockIdx.x * blockDim.x + threadIdx.x;
    if (e >= n_edges) return;
    int d = load_idx(dst, e);
    int s = load_idx(src, e);
    int pos = atomicAdd(&g_cursor[d], 1);
    g_csr_src[pos] = s;
}

// ---------------------------------------------------------------------------
// Accumulate: one warp per dst node.
//   h[d] = (1+eps)*feat[d] + sum_{j in N(d)} feat[src_j]
// Gathers hit L2 (feature 25.6MB L2-resident); h written ONCE (no atomics).
// ---------------------------------------------------------------------------
__global__ void accumulate_kernel(const float* __restrict__ feat,
                                  const float* __restrict__ eps, int n) {
    int d = blockIdx.x * 8 + (threadIdx.x >> 5);
    if (d >= n) return;
    int lane = threadIdx.x & 31;
    float s = 1.0f + eps[0];
    const float4* f4 = (const float4*)feat;

    float4 acc = f4[(size_t)d * 32 + lane];
    acc.x *= s; acc.y *= s; acc.z *= s; acc.w *= s;

    int j = g_csr_off[d], end = g_csr_off[d + 1];
    // 2-way unroll for MLP
    for (; j + 1 < end; j += 2) {
        int s0 = g_csr_src[j];
        int s1 = g_csr_src[j + 1];
        float4 v0 = f4[(size_t)s0 * 32 + lane];
        float4 v1 = f4[(size_t)s1 * 32 + lane];
        acc.x += v0.x + v1.x;
        acc.y += v0.y + v1.y;
        acc.z += v0.z + v1.z;
        acc.w += v0.w + v1.w;
    }
    if (j < end) {
        float4 v0 = f4[(size_t)g_csr_src[j] * 32 + lane];
        acc.x += v0.x; acc.y += v0.y; acc.z += v0.z; acc.w += v0.w;
    }
    ((float4*)g_agg)[(size_t)d * 32 + lane] = acc;
}

// ---------------------------------------------------------------------------
// GEMM: out = relu(h @ W^T + b). Persistent, TILE_M=64, 512 thr, 2 CTA/SM.
// ---------------------------------------------------------------------------
#define TILE_M 64
#define WPAD 132
#define GEMM_BLOCKS 296

__global__ __launch_bounds__(512, 2) void gin_gemm_kernel(
    const float* __restrict__ W, const float* __restrict__ bias,
    float* __restrict__ out, int n_nodes) {
    extern __shared__ float sm[];
    float* Wt = sm;               // [128][WPAD]  Wt[k][c] = W[c][k]
    float* hs = sm + D * WPAD;    // [TILE_M][128]

    int tid = threadIdx.x;
    int tx = tid & 31;
    int ty = tid >> 5;

    for (int idx = tid; idx < D * D; idx += 512) {
        int c = idx >> 7;
        int k = idx & 127;
        Wt[k * WPAD + c] = W[idx];
    }

    float4 bv = *(const float4*)&bias[tx * 4];
    int n_tiles = (n_nodes + TILE_M - 1) / TILE_M;

    for (int t = blockIdx.x; t < n_tiles; t += gridDim.x) {
        int m0 = t * TILE_M;

        __syncthreads();
        for (int idx = tid; idx < TILE_M * (D / 4); idx += 512) {
            int m  = idx >> 5;
            int k4 = idx & 31;
            float4 v = make_float4(0.f, 0.f, 0.f, 0.f);
            if (m0 + m < n_nodes)
                v = ((const float4*)(g_agg + (size_t)(m0 + m) * D))[k4];
            ((float4*)(hs + m * D))[k4] = v;
        }
        __syncthreads();

        float acc[4][4];
#pragma unroll
        for (int i = 0; i < 4; i++)
#pragma unroll
            for (int j = 0; j < 4; j++) acc[i][j] = 0.f;

#pragma unroll 4
        for (int k = 0; k < D; k += 4) {
            float4 w0 = *(const float4*)&Wt[(k + 0) * WPAD + tx * 4];
            float4 w1 = *(const float4*)&Wt[(k + 1) * WPAD + tx * 4];
            float4 w2 = *(const float4*)&Wt[(k + 2) * WPAD + tx * 4];
            float4 w3 = *(const float4*)&Wt[(k + 3) * WPAD + tx * 4];
#pragma unroll
            for (int i = 0; i < 4; i++) {
                float4 hv = *(const float4*)&hs[(ty * 4 + i) * D + k];
                acc[i][0] += hv.x * w0.x + hv.y * w1.x + hv.z * w2.x + hv.w * w3.x;
                acc[i][1] += hv.x * w0.y + hv.y * w1.y + hv.z * w2.y + hv.w * w3.y;
                acc[i][2] += hv.x * w0.z + hv.y * w1.z + hv.z * w2.z + hv.w * w3.z;
                acc[i][3] += hv.x * w0.w + hv.y * w1.w + hv.z * w2.w + hv.w * w3.w;
            }
        }

#pragma unroll
        for (int i = 0; i < 4; i++) {
            int row = m0 + ty * 4 + i;
            if (row < n_nodes) {
                float4 o;
                o.x = fmaxf(acc[i][0] + bv.x, 0.f);
                o.y = fmaxf(acc[i][1] + bv.y, 0.f);
                o.z = fmaxf(acc[i][2] + bv.z, 0.f);
                o.w = fmaxf(acc[i][3] + bv.w, 0.f);
                ((float4*)(out + (size_t)row * D))[tx] = o;
            }
        }
    }
}

// ---------------------------------------------------------------------------
// Launch: detect -> CSR build -> accumulate -> gemm. Graph-capturable.
// ---------------------------------------------------------------------------
extern "C" void kernel_launch(void* const* d_in, const int* in_sizes, int n_in,
                              void* d_out, int out_size) {
    const float* feature = (const float*)d_in[0];
    const void*  src     = d_in[1];
    const void*  dst     = d_in[2];
    const float* W       = (const float*)d_in[3];
    const float* bias    = (const float*)d_in[4];
    const float* eps     = (const float*)d_in[5];
    float*       out     = (float*)d_out;

    int n_nodes = in_sizes[0] / D;
    int n_edges = in_sizes[1];

    static bool smem_ok = false;
    size_t smem = (size_t)(D * WPAD + TILE_M * D) * sizeof(float);  // ~100KB
    if (!smem_ok) {
        cudaFuncSetAttribute(gin_gemm_kernel,
                             cudaFuncAttributeMaxDynamicSharedMemorySize,
                             (int)smem);
        smem_ok = true;
    }

    int nblk_scan = (n_nodes + SCAN_B - 1) / SCAN_B;  // 49 for 50k

    // 0. index dtype detection
    detect_idx_dtype_kernel<<<1, 128>>>(src, n_edges);

    // 1. CSR build
    zero_deg_kernel<<<(n_nodes + 255) / 256, 256>>>(n_nodes);
    hist_kernel<<<(n_edges + 255) / 256, 256>>>(dst, n_edges);
    scan1_kernel<<<nblk_scan, SCAN_B>>>(n_nodes);
    scan2_kernel<<<1, 64>>>(nblk_scan);
    scan3_kernel<<<(n_nodes + 255) / 256, 256>>>(n_nodes);
    reorder_kernel<<<(n_edges + 255) / 256, 256>>>(src, dst, n_edges);

    // 2. gather-accumulate: h = (1+eps)*feat + segment_sum (no atomics on h)
    accumulate_kernel<<<(n_nodes + 7) / 8, 256>>>(feature, eps, n_nodes);

    // 3. persistent fused GEMM + bias + relu
    gin_gemm_kernel<<<GEMM_BLOCKS, 512, smem>>>(W, bias, out, n_nodes);
}

// round 7
// speedup vs baseline: 1.5892x; 1.0716x over previous
#include <cuda_runtime.h>
#include <cuda_bf16.h>

#define NODES_MAX 50048
#define EMAX      2000000
#define D 128
#define SCAN_B 1024

// Scratch (alloc-free rule -> __device__ globals)
__device__ int g_idx_is_i64;
__device__ int g_deg[NODES_MAX];
__device__ int g_scan[NODES_MAX];        // per-block inclusive scans
__device__ int g_blk[64];                // block sums
__device__ int g_blk_exc[64];            // exclusive block offsets
__device__ int g_csr_off[NODES_MAX + 1];
__device__ int g_cursor[NODES_MAX];
__device__ int g_csr_src[EMAX];

__device__ __forceinline__ int load_idx(const void* p, int e) {
    return g_idx_is_i64 ? (int)((const long long*)p)[e] : ((const int*)p)[e];
}

// ---------------------------------------------------------------------------
// Kernel 1: zero degree counters; block 0 additionally detects index dtype
// (int64 indices < 50000 have all-zero high words; int32 data does not).
// ---------------------------------------------------------------------------
__global__ void zero_detect_kernel(const void* __restrict__ src,
                                   int n, int n_edges) {
    int i = blockIdx.x * blockDim.x + threadIdx.x;
    if (i < n) g_deg[i] = 0;
    if (blockIdx.x == 0) {
        __shared__ int any_hi;
        if (threadIdx.x == 0) any_hi = 0;
        __syncthreads();
        int nsample = n_edges < 128 ? n_edges : 128;
        if (threadIdx.x < nsample) {
            int hi = ((const int*)src)[2 * threadIdx.x + 1];
            if (hi != 0) atomicOr(&any_hi, 1);
        }
        __syncthreads();
        if (threadIdx.x == 0) g_idx_is_i64 = any_hi ? 0 : 1;
    }
}

// ---------------------------------------------------------------------------
// CSR construction: histogram -> scan(x3) -> reorder
// ---------------------------------------------------------------------------
__global__ void hist_kernel(const void* __restrict__ dst, int n_edges) {
    int e = blockIdx.x * blockDim.x + threadIdx.x;
    if (e >= n_edges) return;
    atomicAdd(&g_deg[load_idx(dst, e)], 1);
}

// Per-block inclusive Hillis-Steele scan of g_deg.
__global__ void scan1_kernel(int n) {
    __shared__ int s[SCAN_B];
    int t = threadIdx.x;
    int i = blockIdx.x * SCAN_B + t;
    int v = (i < n) ? g_deg[i] : 0;
    s[t] = v;
    __syncthreads();
    for (int o = 1; o < SCAN_B; o <<= 1) {
        int x = (t >= o) ? s[t - o] : 0;
        __syncthreads();
        s[t] += x;
        __syncthreads();
    }
    if (i < n) g_scan[i] = s[t];
    if (t == SCAN_B - 1) g_blk[blockIdx.x] = s[t];
}

// Single-block scan of block sums -> exclusive block offsets.
__global__ void scan2_kernel(int nblk) {
    __shared__ int s[64];
    int t = threadIdx.x;
    int v = (t < nblk) ? g_blk[t] : 0;
    s[t] = v;
    __syncthreads();
    for (int o = 1; o < 64; o <<= 1) {
        int x = (t >= o) ? s[t - o] : 0;
        __syncthreads();
        s[t] += x;
        __syncthreads();
    }
    if (t < nblk) g_blk_exc[t] = s[t] - v;
}

// Combine: exclusive global offsets; init cursors; write sentinel.
__global__ void scan3_kernel(int n) {
    int i = blockIdx.x * blockDim.x + threadIdx.x;
    if (i >= n) return;
    int off = g_blk_exc[i / SCAN_B] + g_scan[i] - g_deg[i];
    g_csr_off[i] = off;
    g_cursor[i]  = off;
    if (i == n - 1) g_csr_off[n] = off + g_deg[i];
}

__global__ void reorder_kernel(const void* __restrict__ src,
                               const void* __restrict__ dst, int n_edges) {
    int e = blockIdx.x * blockDim.x + threadIdx.x;
    if (e >= n_edges) return;
    int d = load_idx(dst, e);
    int s = load_idx(src, e);
    int pos = atomicAdd(&g_cursor[d], 1);
    g_csr_src[pos] = s;
}

// ---------------------------------------------------------------------------
// FUSED kernel: out = relu( ((1+eps)*feat + segsum(feat,csr)) @ W^T + b )
// Persistent, TILE_M=64 tiles, 512 threads, 2 CTA/SM.
// Phase A: 16 warps gather-accumulate h rows straight into smem (no g_agg
//          round trip). Phase B: 4x4 register-tile FFMA GEMM from smem.
// With 2 CTAs/SM, one CTA's FFMA phase overlaps the other's gather phase.
// ---------------------------------------------------------------------------
#define TILE_M 64
#define WPAD 132
#define GEMM_BLOCKS 296

__global__ __launch_bounds__(512, 2) void gin_fused_kernel(
    const float* __restrict__ feat, const float* __restrict__ W,
    const float* __restrict__ bias, const float* __restrict__ eps,
    float* __restrict__ out, int n_nodes) {
    extern __shared__ float sm[];
    float* Wt = sm;               // [128][WPAD]  Wt[k][c] = W[c][k]
    float* hs = sm + D * WPAD;    // [TILE_M][128]

    int tid  = threadIdx.x;
    int lane = tid & 31;
    int wid  = tid >> 5;          // 0..15
    int tx = lane;                // GEMM: output cols 4*tx..4*tx+3
    int ty = wid;                 // GEMM: rows 4*ty..4*ty+3
    float s = 1.0f + eps[0];
    const float4* f4 = (const float4*)feat;

    // Stage W transposed once per block.
    for (int idx = tid; idx < D * D; idx += 512) {
        int c = idx >> 7;
        int k = idx & 127;
        Wt[k * WPAD + c] = W[idx];
    }

    float4 bv = *(const float4*)&bias[tx * 4];
    int n_tiles = (n_nodes + TILE_M - 1) / TILE_M;

    for (int t = blockIdx.x; t < n_tiles; t += gridDim.x) {
        int m0 = t * TILE_M;

        __syncthreads();   // prev iteration's readers done with hs

        // ---- Phase A: gather-accumulate h rows into smem -------------
        // Warp w builds rows w, w+16, w+32, w+48 of the tile.
        for (int r = wid; r < TILE_M; r += 16) {
            int row = m0 + r;
            float4 acc = make_float4(0.f, 0.f, 0.f, 0.f);
            if (row < n_nodes) {
                acc = f4[(size_t)row * 32 + lane];
                acc.x *= s; acc.y *= s; acc.z *= s; acc.w *= s;
                int j = g_csr_off[row], end = g_csr_off[row + 1];
                for (; j + 1 < end; j += 2) {      // 2-way unroll for MLP
                    int s0 = g_csr_src[j];
                    int s1 = g_csr_src[j + 1];
                    float4 v0 = f4[(size_t)s0 * 32 + lane];
                    float4 v1 = f4[(size_t)s1 * 32 + lane];
                    acc.x += v0.x + v1.x;
                    acc.y += v0.y + v1.y;
                    acc.z += v0.z + v1.z;
                    acc.w += v0.w + v1.w;
                }
                if (j < end) {
                    float4 v0 = f4[(size_t)g_csr_src[j] * 32 + lane];
                    acc.x += v0.x; acc.y += v0.y;
                    acc.z += v0.z; acc.w += v0.w;
                }
            }
            ((float4*)(hs + r * D))[lane] = acc;
        }
        __syncthreads();

        // ---- Phase B: 4x4 register-tile GEMM from smem ---------------
        float acc[4][4];
#pragma unroll
        for (int i = 0; i < 4; i++)
#pragma unroll
            for (int j = 0; j < 4; j++) acc[i][j] = 0.f;

#pragma unroll 4
        for (int k = 0; k < D; k += 4) {
            float4 w0 = *(const float4*)&Wt[(k + 0) * WPAD + tx * 4];
            float4 w1 = *(const float4*)&Wt[(k + 1) * WPAD + tx * 4];
            float4 w2 = *(const float4*)&Wt[(k + 2) * WPAD + tx * 4];
            float4 w3 = *(const float4*)&Wt[(k + 3) * WPAD + tx * 4];
#pragma unroll
            for (int i = 0; i < 4; i++) {
                float4 hv = *(const float4*)&hs[(ty * 4 + i) * D + k];
                acc[i][0] += hv.x * w0.x + hv.y * w1.x + hv.z * w2.x + hv.w * w3.x;
                acc[i][1] += hv.x * w0.y + hv.y * w1.y + hv.z * w2.y + hv.w * w3.y;
                acc[i][2] += hv.x * w0.z + hv.y * w1.z + hv.z * w2.z + hv.w * w3.z;
                acc[i][3] += hv.x * w0.w + hv.y * w1.w + hv.z * w2.w + hv.w * w3.w;
            }
        }

#pragma unroll
        for (int i = 0; i < 4; i++) {
            int row = m0 + ty * 4 + i;
            if (row < n_nodes) {
                float4 o;
                o.x = fmaxf(acc[i][0] + bv.x, 0.f);
                o.y = fmaxf(acc[i][1] + bv.y, 0.f);
                o.z = fmaxf(acc[i][2] + bv.z, 0.f);
                o.w = fmaxf(acc[i][3] + bv.w, 0.f);
                ((float4*)(out + (size_t)row * D))[tx] = o;
            }
        }
    }
}

// ---------------------------------------------------------------------------
// Launch: zero+detect -> hist -> scan x3 -> reorder -> fused gemm.
// Graph-capturable, alloc-free.
// ---------------------------------------------------------------------------
extern "C" void kernel_launch(void* const* d_in, const int* in_sizes, int n_in,
                              void* d_out, int out_size) {
    const float* feature = (const float*)d_in[0];
    const void*  src     = d_in[1];
    const void*  dst     = d_in[2];
    const float* W       = (const float*)d_in[3];
    const float* bias    = (const float*)d_in[4];
    const float* eps     = (const float*)d_in[5];
    float*       out     = (float*)d_out;

    int n_nodes = in_sizes[0] / D;
    int n_edges = in_sizes[1];

    static bool smem_ok = false;
    size_t smem = (size_t)(D * WPAD + TILE_M * D) * sizeof(float);  // ~100KB
    if (!smem_ok) {
        cudaFuncSetAttribute(gin_fused_kernel,
                             cudaFuncAttributeMaxDynamicSharedMemorySize,
                             (int)smem);
        smem_ok = true;
    }

    int nblk_scan = (n_nodes + SCAN_B - 1) / SCAN_B;  // 49 for 50k

    // CSR build
    zero_detect_kernel<<<(n_nodes + 255) / 256, 256>>>(src, n_nodes, n_edges);
    hist_kernel<<<(n_edges + 255) / 256, 256>>>(dst, n_edges);
    scan1_kernel<<<nblk_scan, SCAN_B>>>(n_nodes);
    scan2_kernel<<<1, 64>>>(nblk_scan);
    scan3_kernel<<<(n_nodes + 255) / 256, 256>>>(n_nodes);
    reorder_kernel<<<(n_edges + 255) / 256, 256>>>(src, dst, n_edges);

    // Fused gather-accumulate + GEMM + bias + relu
    gin_fused_kernel<<<GEMM_BLOCKS, 512, smem>>>(
        feature, W, bias, eps, out, n_nodes);
}